// round 4
// baseline (speedup 1.0000x reference)
#include <cuda_runtime.h>

#define NB 2
#define NC 128
#define NH 64
#define NW 64
#define NG 8
#define NPIX 4096
#define HP 78
#define PP (78*78)

// Scratch: Q in [b][g][cq][pix] float4 layout; K/V padded by 7 on each side:
// [b][g][cq][yp][xp] float4 (cq = channel quad within the 16-channel group).
__device__ float4 g_Q[NB*NG*4*NPIX];
__device__ float4 g_K[NB*NG*4*PP];
__device__ float4 g_V[NB*NG*4*PP];

__global__ void zero_kv_kernel() {
    int i = blockIdx.x * blockDim.x + threadIdx.x;
    const int n = NB*NG*4*PP;
    if (i < n) {
        float4 z = make_float4(0.f, 0.f, 0.f, 0.f);
        g_K[i] = z;
        g_V[i] = z;
    }
}

// One block: 64 pixels x 128 output channels for one of {Q,K,V} (blockIdx.z).
// Thread: 4 pixels (float4 input loads) x 8 outputs. 256 threads.
__global__ __launch_bounds__(256) void qkv_kernel(
    const float* __restrict__ fm,
    const float* __restrict__ wq,
    const float* __restrict__ wk,
    const float* __restrict__ wv)
{
    const int m = blockIdx.z;           // 0=Q, 1=K, 2=V
    const int b = blockIdx.y;
    const int pixbase = blockIdx.x * 64;
    const int tid = threadIdx.x;
    const int p4 = tid & 15;            // pixel quad 0..15
    const int og = tid >> 4;            // output octet 0..15

    const float* W = (m == 0) ? wq : (m == 1) ? wk : wv;
    // Q reads fm_t1 (channels 128..255); K,V read fm_t0 (channels 0..127).
    const float* xin = fm + ((size_t)b*2*NC + (m == 0 ? NC : 0))*NPIX + pixbase + p4*4;
    const float* Wb = W + og*8*NC;

    float acc[8][4];
    #pragma unroll
    for (int k = 0; k < 8; k++) {
        acc[k][0] = acc[k][1] = acc[k][2] = acc[k][3] = 0.f;
    }

    #pragma unroll 2
    for (int c4 = 0; c4 < 32; c4++) {
        float4 xv[4];
        #pragma unroll
        for (int cc = 0; cc < 4; cc++)
            xv[cc] = *reinterpret_cast<const float4*>(xin + (size_t)(c4*4 + cc)*NPIX);
        #pragma unroll
        for (int k = 0; k < 8; k++) {
            float4 w4 = *reinterpret_cast<const float4*>(Wb + k*NC + c4*4);
            acc[k][0] += w4.x*xv[0].x + w4.y*xv[1].x + w4.z*xv[2].x + w4.w*xv[3].x;
            acc[k][1] += w4.x*xv[0].y + w4.y*xv[1].y + w4.z*xv[2].y + w4.w*xv[3].y;
            acc[k][2] += w4.x*xv[0].z + w4.y*xv[1].z + w4.z*xv[2].z + w4.w*xv[3].z;
            acc[k][3] += w4.x*xv[0].w + w4.y*xv[1].w + w4.z*xv[2].w + w4.w*xv[3].w;
        }
    }

    const int o0 = og * 8;
    const int g = o0 >> 4;
    const int cq0 = (o0 & 15) >> 2;     // 0 or 2
    #pragma unroll
    for (int pi = 0; pi < 4; pi++) {
        int pixel = pixbase + p4*4 + pi;
        float4 v0 = make_float4(acc[0][pi], acc[1][pi], acc[2][pi], acc[3][pi]);
        float4 v1 = make_float4(acc[4][pi], acc[5][pi], acc[6][pi], acc[7][pi]);
        if (m == 0) {
            int base = ((b*NG + g)*4)*NPIX + pixel;
            g_Q[base + cq0*NPIX] = v0;
            g_Q[base + (cq0 + 1)*NPIX] = v1;
        } else {
            int y = pixel >> 6, x = pixel & 63;
            int off = (y + 7)*HP + (x + 7);
            float4* dst = (m == 1) ? g_K : g_V;
            int base = ((b*NG + g)*4)*PP + off;
            dst[base + cq0*PP] = v0;
            dst[base + (cq0 + 1)*PP] = v1;
        }
    }
}

// One thread per (b, g, y, x). Warp spans 32 consecutive x -> coalesced float4.
__global__ __launch_bounds__(256) void attn_kernel(
    const float* __restrict__ rel_h,
    const float* __restrict__ rel_w,
    float* __restrict__ out)
{
    int t = blockIdx.x * 256 + threadIdx.x;
    int x = t & 63;
    int y = (t >> 6) & 63;
    int g = (t >> 12) & 7;
    int b = t >> 15;
    int pix = y*NW + x;

    const float4* Qp = g_Q + ((b*NG + g)*4)*NPIX;
    const float4* Kp = g_K + ((b*NG + g)*4)*PP;
    const float4* Vp = g_V + ((b*NG + g)*4)*PP;

    float qa[16];
    #pragma unroll
    for (int cq = 0; cq < 4; cq++) {
        float4 qv = Qp[cq*NPIX + pix];
        qa[cq*4+0] = qv.x; qa[cq*4+1] = qv.y; qa[cq*4+2] = qv.z; qa[cq*4+3] = qv.w;
    }

    // rel bias: groups 0..3 use rel_h (depends on window row i),
    // groups 4..7 use rel_w (depends on window col j).
    const float* rel = (g < 4) ? (rel_h + g*16*7) : (rel_w + (g - 4)*16*7);
    float bias[7];
    #pragma unroll
    for (int i = 0; i < 7; i++) {
        float s = 0.f;
        #pragma unroll
        for (int c = 0; c < 16; c++) s += qa[c] * rel[c*7 + i];
        bias[i] = s;
    }
    const bool useI = (g < 4);

    float oa[16];
    #pragma unroll
    for (int c = 0; c < 16; c++) oa[c] = 0.f;

    // ---- main 7x7 window (pad 3 -> padded-7 coords y+4+i, x+4+j) ----
    {
        float lg[49];
        float mx = -1e30f;
        #pragma unroll
        for (int i = 0; i < 7; i++) {
            #pragma unroll
            for (int j = 0; j < 7; j++) {
                int off = (y + 4 + i)*HP + (x + 4 + j);
                float d = useI ? bias[i] : bias[j];
                #pragma unroll
                for (int cq = 0; cq < 4; cq++) {
                    float4 kv = Kp[cq*PP + off];
                    d += qa[cq*4+0]*kv.x + qa[cq*4+1]*kv.y
                       + qa[cq*4+2]*kv.z + qa[cq*4+3]*kv.w;
                }
                lg[i*7 + j] = d;
                mx = fmaxf(mx, d);
            }
        }
        float s = 0.f;
        #pragma unroll
        for (int k = 0; k < 49; k++) { float e = __expf(lg[k] - mx); lg[k] = e; s += e; }
        float inv = 1.0f / s;
        #pragma unroll
        for (int i = 0; i < 7; i++) {
            #pragma unroll
            for (int j = 0; j < 7; j++) {
                int off = (y + 4 + i)*HP + (x + 4 + j);
                float w = lg[i*7 + j] * inv;
                #pragma unroll
                for (int cq = 0; cq < 4; cq++) {
                    float4 vv = Vp[cq*PP + off];
                    oa[cq*4+0] += w*vv.x; oa[cq*4+1] += w*vv.y;
                    oa[cq*4+2] += w*vv.z; oa[cq*4+3] += w*vv.w;
                }
            }
        }
    }

    // ---- refine: row (15 taps along W, fixed row) ----
    {
        float lg[15];
        float mx = -1e30f;
        #pragma unroll
        for (int j = 0; j < 15; j++) {
            int off = (y + 7)*HP + (x + j);
            float d = 0.f;
            #pragma unroll
            for (int cq = 0; cq < 4; cq++) {
                float4 kv = Kp[cq*PP + off];
                d += qa[cq*4+0]*kv.x + qa[cq*4+1]*kv.y
                   + qa[cq*4+2]*kv.z + qa[cq*4+3]*kv.w;
            }
            lg[j] = d;
            mx = fmaxf(mx, d);
        }
        float s = 0.f;
        #pragma unroll
        for (int j = 0; j < 15; j++) { float e = __expf(lg[j] - mx); lg[j] = e; s += e; }
        float inv = 1.0f / s;
        #pragma unroll
        for (int j = 0; j < 15; j++) {
            int off = (y + 7)*HP + (x + j);
            float w = lg[j] * inv;
            #pragma unroll
            for (int cq = 0; cq < 4; cq++) {
                float4 vv = Vp[cq*PP + off];
                oa[cq*4+0] += w*vv.x; oa[cq*4+1] += w*vv.y;
                oa[cq*4+2] += w*vv.z; oa[cq*4+3] += w*vv.w;
            }
        }
    }

    // ---- refine: col (15 taps along H, fixed col) ----
    {
        float lg[15];
        float mx = -1e30f;
        #pragma unroll
        for (int j = 0; j < 15; j++) {
            int off = (y + j)*HP + (x + 7);
            float d = 0.f;
            #pragma unroll
            for (int cq = 0; cq < 4; cq++) {
                float4 kv = Kp[cq*PP + off];
                d += qa[cq*4+0]*kv.x + qa[cq*4+1]*kv.y
                   + qa[cq*4+2]*kv.z + qa[cq*4+3]*kv.w;
            }
            lg[j] = d;
            mx = fmaxf(mx, d);
        }
        float s = 0.f;
        #pragma unroll
        for (int j = 0; j < 15; j++) { float e = __expf(lg[j] - mx); lg[j] = e; s += e; }
        float inv = 1.0f / s;
        #pragma unroll
        for (int j = 0; j < 15; j++) {
            int off = (y + j)*HP + (x + 7);
            float w = lg[j] * inv;
            #pragma unroll
            for (int cq = 0; cq < 4; cq++) {
                float4 vv = Vp[cq*PP + off];
                oa[cq*4+0] += w*vv.x; oa[cq*4+1] += w*vv.y;
                oa[cq*4+2] += w*vv.z; oa[cq*4+3] += w*vv.w;
            }
        }
    }

    // write out: out[b][g*16+c][y][x]
    float* ob = out + ((size_t)b*NC + g*16)*NPIX + pix;
    #pragma unroll
    for (int c = 0; c < 16; c++) ob[c*NPIX] = oa[c];
}

extern "C" void kernel_launch(void* const* d_in, const int* in_sizes, int n_in,
                              void* d_out, int out_size) {
    const float* fm = (const float*)d_in[0];
    const float* wq = (const float*)d_in[1];
    const float* wk = (const float*)d_in[2];
    const float* wv = (const float*)d_in[3];
    const float* rh = (const float*)d_in[4];
    const float* rw = (const float*)d_in[5];
    float* out = (float*)d_out;

    const int nz = NB*NG*4*PP;
    zero_kv_kernel<<<(nz + 255) / 256, 256>>>();

    dim3 grid(64, NB, 3);
    qkv_kernel<<<grid, 256>>>(fm, wq, wk, wv);

    attn_kernel<<<256, 256>>>(rh, rw, out);
}